// round 12
// baseline (speedup 1.0000x reference)
#include <cuda_runtime.h>
#include <cuda_fp16.h>
#include <math.h>
#include <cstdint>

#define BB 8
#define SS 1024
#define EE 128
#define HH 16
#define BHN 128
#define FF 6144

#define QPH 136    // pitch (halves) for 128-wide half tiles
#define VPH64 72   // pitch (halves) for 64-wide half tiles (V^T)
#define CPIT 132   // pitch (floats) for QKV C staging / attn combine

// Scratch (fp16): q,k in [bh][s][d]; v transposed in [bh][d][s]
__device__ __half g_q [(size_t)BHN*SS*EE];
__device__ __half g_k [(size_t)BHN*SS*EE];
__device__ __half g_vT[(size_t)BHN*EE*SS];
__device__ float  g_cs[SS*64];
__device__ float  g_sn[SS*64];

__device__ __forceinline__ void mma16(float d[4], const uint32_t a[4],
                                      const uint32_t b[2]) {
    asm volatile(
        "mma.sync.aligned.m16n8k16.row.col.f32.f16.f16.f32 "
        "{%0,%1,%2,%3}, {%4,%5,%6,%7}, {%8,%9}, {%0,%1,%2,%3};"
        : "+f"(d[0]), "+f"(d[1]), "+f"(d[2]), "+f"(d[3])
        : "r"(a[0]), "r"(a[1]), "r"(a[2]), "r"(a[3]), "r"(b[0]), "r"(b[1]));
}

__device__ __forceinline__ uint32_t ldh2(const __half* p) {
    return *(const uint32_t*)p;
}

__device__ __forceinline__ uint32_t smem_u32(const void* p) {
    uint32_t a;
    asm("{ .reg .u64 t; cvta.to.shared.u64 t, %1; cvt.u32.u64 %0, t; }"
        : "=r"(a) : "l"(p));
    return a;
}

__device__ __forceinline__ void cpa16(uint32_t dst, const void* src) {
    asm volatile("cp.async.cg.shared.global [%0], [%1], 16;"
                 :: "r"(dst), "l"(src));
}
#define CP_COMMIT() asm volatile("cp.async.commit_group;" ::: "memory")
#define CP_WAIT0()  asm volatile("cp.async.wait_group 0;"  ::: "memory")

__device__ __forceinline__ uint4 pack8(float4 x, float4 y) {
    __half2 h0 = __floats2half2_rn(x.x, x.y);
    __half2 h1 = __floats2half2_rn(x.z, x.w);
    __half2 h2 = __floats2half2_rn(y.x, y.y);
    __half2 h3 = __floats2half2_rn(y.z, y.w);
    uint4 u;
    u.x = *(uint32_t*)&h0; u.y = *(uint32_t*)&h1;
    u.z = *(uint32_t*)&h2; u.w = *(uint32_t*)&h3;
    return u;
}

// ===========================================================================
// Kernel 0: RoPE table
// ===========================================================================
__global__ void rope_table_kernel() {
    int idx = blockIdx.x * blockDim.x + threadIdx.x;
    if (idx >= SS * 64) return;
    int s = idx >> 6, j = idx & 63;
    float invf = (float)pow(10000.0, -(double)j / 64.0);
    float ang = (float)s * invf;
    float sn, cs;
    sincosf(ang, &sn, &cs);
    g_cs[idx] = cs;
    g_sn[idx] = sn;
}

// ===========================================================================
// Kernel 1: QKV = X @ W^T + b (fp16 mma), fused RoPE, scatter q/k/vT.
// ===========================================================================
__global__ void __launch_bounds__(256, 2) qkv_kernel(
    const float* __restrict__ X, const float* __restrict__ W,
    const float* __restrict__ bias)
{
    extern __shared__ char smraw[];
    __half* Ah = (__half*)smraw;            // [128][QPH]
    __half* Bh = Ah + 128 * QPH;            // [128][QPH]
    float*  Cs = (float*)smraw;             // [128][CPIT] (reused after gemm)

    const int tid = threadIdx.x, wid = tid >> 5, lane = tid & 31;
    const int g = lane >> 2, t = lane & 3;
    const int wm = wid & 3, wn = wid >> 2;
    const int nt = blockIdx.x, mt = blockIdx.y;

    const float* Ag = X + (size_t)mt * 128 * EE;
    const float* Bg = W + (size_t)nt * 128 * EE;

#pragma unroll
    for (int i = 0; i < 8; i++) {
        int seg = tid + i * 256;
        int r = seg >> 4, c8 = (seg & 15) << 3;
        float4 a1 = *(const float4*)&Ag[r * EE + c8];
        float4 a2 = *(const float4*)&Ag[r * EE + c8 + 4];
        *(uint4*)&Ah[r * QPH + c8] = pack8(a1, a2);
        float4 b1 = *(const float4*)&Bg[r * EE + c8];
        float4 b2 = *(const float4*)&Bg[r * EE + c8 + 4];
        *(uint4*)&Bh[r * QPH + c8] = pack8(b1, b2);
    }
    __syncthreads();

    float acc[2][8][4];
#pragma unroll
    for (int mi = 0; mi < 2; mi++)
#pragma unroll
        for (int ni = 0; ni < 8; ni++)
#pragma unroll
            for (int ci = 0; ci < 4; ci++) acc[mi][ni][ci] = 0.0f;

    const __half* Ab = Ah + (wm * 32 + g) * QPH + 2 * t;
    const __half* Bb = Bh + (wn * 64 + g) * QPH + 2 * t;

#pragma unroll
    for (int k0 = 0; k0 < 8; k0++) {
        uint32_t af[2][4], bf[8][2];
#pragma unroll
        for (int mi = 0; mi < 2; mi++) {
            const __half* p = Ab + mi * 16 * QPH + k0 * 16;
            af[mi][0] = ldh2(p);
            af[mi][1] = ldh2(p + 8 * QPH);
            af[mi][2] = ldh2(p + 8);
            af[mi][3] = ldh2(p + 8 * QPH + 8);
        }
#pragma unroll
        for (int ni = 0; ni < 8; ni++) {
            const __half* p = Bb + ni * 8 * QPH + k0 * 16;
            bf[ni][0] = ldh2(p);
            bf[ni][1] = ldh2(p + 8);
        }
#pragma unroll
        for (int mi = 0; mi < 2; mi++)
#pragma unroll
            for (int ni = 0; ni < 8; ni++)
                mma16(acc[mi][ni], af[mi], bf[ni]);
    }
    __syncthreads();

#pragma unroll
    for (int mi = 0; mi < 2; mi++)
#pragma unroll
        for (int ni = 0; ni < 8; ni++) {
            int row = wm * 32 + mi * 16 + g;
            int col = wn * 64 + ni * 8 + t * 2;
            *(float2*)&Cs[row * CPIT + col] =
                make_float2(acc[mi][ni][0], acc[mi][ni][1]);
            *(float2*)&Cs[(row + 8) * CPIT + col] =
                make_float2(acc[mi][ni][2], acc[mi][ni][3]);
        }
    __syncthreads();

    const int c = nt >> 4, h = nt & 15;
    const float* bptr = bias + nt * 128;
    const int bidx = (mt * 128) >> 10;
    const int s_base = (mt * 128) & 1023;

    if (c == 2) {
        size_t vb = ((size_t)(bidx * HH + h)) * EE * SS;
#pragma unroll
        for (int it = 0; it < 16; it++) {
            int d = it * 8 + wid;
            float bd = bptr[d];
#pragma unroll
            for (int q = 0; q < 4; q++) {
                int r = q * 32 + lane;
                g_vT[vb + (size_t)d * SS + s_base + r] =
                    __float2half_rn(Cs[r * CPIT + d] + bd);
            }
        }
    } else {
        __half* dst = (c == 0) ? g_q : g_k;
        const int row = tid >> 1, part = tid & 1;
        const int s = s_base + row;
        size_t rb = (((size_t)(bidx * HH + h)) * SS + s) * EE;
#pragma unroll
        for (int jq = 0; jq < 8; jq++) {
            int j = part * 32 + jq * 4;
            float4 x1 = *(float4*)&Cs[row * CPIT + j];
            float4 x2 = *(float4*)&Cs[row * CPIT + 64 + j];
            float4 b1 = *(const float4*)&bptr[j];
            float4 b2 = *(const float4*)&bptr[64 + j];
            float4 cs4 = *(const float4*)&g_cs[s * 64 + j];
            float4 sn4 = *(const float4*)&g_sn[s * 64 + j];
            x1.x += b1.x; x1.y += b1.y; x1.z += b1.z; x1.w += b1.w;
            x2.x += b2.x; x2.y += b2.y; x2.z += b2.z; x2.w += b2.w;
            __half2 o1a = __floats2half2_rn(x1.x * cs4.x - x2.x * sn4.x,
                                            x1.y * cs4.y - x2.y * sn4.y);
            __half2 o1b = __floats2half2_rn(x1.z * cs4.z - x2.z * sn4.z,
                                            x1.w * cs4.w - x2.w * sn4.w);
            __half2 o2a = __floats2half2_rn(x1.x * sn4.x + x2.x * cs4.x,
                                            x1.y * sn4.y + x2.y * cs4.y);
            __half2 o2b = __floats2half2_rn(x1.z * sn4.z + x2.z * cs4.z,
                                            x1.w * sn4.w + x2.w * cs4.w);
            uint2 u1 = make_uint2(*(uint32_t*)&o1a, *(uint32_t*)&o1b);
            uint2 u2 = make_uint2(*(uint32_t*)&o2a, *(uint32_t*)&o2b);
            *(uint2*)&dst[rb + j]      = u1;
            *(uint2*)&dst[rb + 64 + j] = u2;
        }
    }
}

// ===========================================================================
// Kernel 2: attention (fp16 mma, FA2 register-P, key-split warp pairs).
// CTA = 64 q rows of one (b,h); 16 iterations of 64 keys, cp.async
// double-buffered. Warp (rg, kpar): rows 16rg..+16, keys 32kpar..+32 of
// each 64-key tile. Warp-private softmax (register P), O in regs; the two
// kpar partials combined once through smem at the end.
// grid = 2048 CTAs -> 6.92 waves @ 2 CTA/SM (vs 3.46->4 before).
// ===========================================================================
#define AQ_OFF   0
#define AK_OFF   17408                       // 2 x [64][QPH] halves (17408 ea)
#define AV_OFF   (17408 + 2*17408)           // 2 x [128][VPH64] halves (18432 ea)
#define ATTN_SMEM (AV_OFF + 2*18432)         // 89088

__global__ void __launch_bounds__(256, 2) attn_kernel(float* __restrict__ out)
{
    extern __shared__ char smraw[];
    __half* Qs = (__half*)(smraw + AQ_OFF);
    __half* Ks = (__half*)(smraw + AK_OFF);
    __half* Vs = (__half*)(smraw + AV_OFF);
    const uint32_t sb = smem_u32(smraw);

    const int tid = threadIdx.x, wid = tid >> 5, lane = tid & 31;
    const int g = lane >> 2, t = lane & 3;
    const int rg = wid & 3, kpar = wid >> 2;
    const int qt = blockIdx.x, bh = blockIdx.y;   // qt: 0..15 (64-row tiles)

    const __half* qg = g_q  + (size_t)bh * SS * EE + (size_t)qt * 64 * EE;
    const __half* kg = g_k  + (size_t)bh * SS * EE;
    const __half* vg = g_vT + (size_t)bh * EE * SS;

    // ---- prologue: K/V tile 0 (cp.async) + Q tile (regular) ----
#pragma unroll
    for (int j = 0; j < 4; j++) {
        int seg = tid + j * 256;                  // K: 64x128h = 1024 chunks
        int kr = seg >> 4, kc = (seg & 15) << 3;
        cpa16(sb + AK_OFF + (kr * QPH + kc) * 2, kg + (size_t)kr * EE + kc);
    }
#pragma unroll
    for (int j = 0; j < 4; j++) {
        int seg = tid + j * 256;                  // V: 128x64h = 1024 chunks
        int vr = seg >> 3, vc = (seg & 7) << 3;
        cpa16(sb + AV_OFF + (vr * VPH64 + vc) * 2, vg + (size_t)vr * SS + vc);
    }
    CP_COMMIT();

#pragma unroll
    for (int i = 0; i < 4; i++) {
        int seg = tid + i * 256;                  // Q: 64x128h = 1024 chunks
        int r = seg >> 4, c8 = (seg & 15) << 3;
        *(uint4*)&Qs[r * QPH + c8] = *(const uint4*)&qg[r * EE + c8];
    }
    CP_WAIT0();
    __syncthreads();

    float accO[16][4];
#pragma unroll
    for (int ni = 0; ni < 16; ni++)
#pragma unroll
        for (int ci = 0; ci < 4; ci++) accO[ni][ci] = 0.0f;
    float l0 = 0.0f, l1 = 0.0f;

    const float scl = 0.08838834764831845f;  // 1/sqrt(128)

    const __half* QA = Qs + (16 * rg + g) * QPH + 2 * t;

    for (int kt = 0; kt < 16; kt++) {
        const int buf = kt & 1;

        // ---- prefetch 64-key tile kt+1 ----
        if (kt < 15) {
            const __half* kgn = kg + (size_t)(kt + 1) * 64 * EE;
            const __half* vgn = vg + (kt + 1) * 64;
            const uint32_t kb = sb + AK_OFF + ((kt + 1) & 1) * 17408;
            const uint32_t vb = sb + AV_OFF + ((kt + 1) & 1) * 18432;
#pragma unroll
            for (int j = 0; j < 4; j++) {
                int seg = tid + j * 256;
                int kr = seg >> 4, kc = (seg & 15) << 3;
                cpa16(kb + (kr * QPH + kc) * 2, kgn + (size_t)kr * EE + kc);
            }
#pragma unroll
            for (int j = 0; j < 4; j++) {
                int seg = tid + j * 256;
                int vr = seg >> 3, vc = (seg & 7) << 3;
                cpa16(vb + (vr * VPH64 + vc) * 2, vgn + (size_t)vr * SS + vc);
            }
            CP_COMMIT();
        }

        const __half* KB = Ks + buf * (64 * QPH)
                              + (kpar * 32 + g) * QPH + 2 * t;
        const __half* VB = Vs + buf * (128 * VPH64)
                              + g * VPH64 + kpar * 32 + 2 * t;

        // ---- gemm1: S(16 rows x 32 keys/warp) = Q . K^T over d=128 ----
        float sc[4][4];
#pragma unroll
        for (int ni = 0; ni < 4; ni++)
#pragma unroll
            for (int ci = 0; ci < 4; ci++) sc[ni][ci] = 0.0f;

#pragma unroll
        for (int k0 = 0; k0 < 8; k0++) {
            uint32_t af[4];
            {
                const __half* p = QA + k0 * 16;
                af[0] = ldh2(p);
                af[1] = ldh2(p + 8 * QPH);
                af[2] = ldh2(p + 8);
                af[3] = ldh2(p + 8 * QPH + 8);
            }
#pragma unroll
            for (int ni = 0; ni < 4; ni++) {
                const __half* p = KB + ni * 8 * QPH + k0 * 16;
                uint32_t bf[2] = {ldh2(p), ldh2(p + 8)};
                mma16(sc[ni], af, bf);
            }
        }

        // ---- softmax numerator in registers; pack as gemm2 A frags ----
        uint32_t pa[2][4];
#pragma unroll
        for (int ni = 0; ni < 4; ni++) {
            float p0 = __expf(sc[ni][0] * scl);
            float p1 = __expf(sc[ni][1] * scl);
            float p2 = __expf(sc[ni][2] * scl);
            float p3 = __expf(sc[ni][3] * scl);
            l0 += p0 + p1;
            l1 += p2 + p3;
            __half2 hA = __floats2half2_rn(p0, p1);
            __half2 hB = __floats2half2_rn(p2, p3);
            const int kg2 = ni >> 1, pos = ni & 1;
            pa[kg2][2 * pos + 0] = *(uint32_t*)&hA;
            pa[kg2][2 * pos + 1] = *(uint32_t*)&hB;
        }

        // ---- gemm2: O(16 x 128/warp) += P . V over this warp's 32 keys ----
#pragma unroll
        for (int kg2 = 0; kg2 < 2; kg2++) {
#pragma unroll
            for (int ni = 0; ni < 16; ni++) {
                const __half* p = VB + ni * 8 * VPH64 + kg2 * 16;
                uint32_t bf[2] = {ldh2(p), ldh2(p + 8)};
                mma16(accO[ni], pa[kg2], bf);
            }
        }

        CP_WAIT0();
        __syncthreads();
    }

    // ---- quad-reduce this warp's row sums ----
    l0 += __shfl_xor_sync(0xffffffffu, l0, 1);
    l0 += __shfl_xor_sync(0xffffffffu, l0, 2);
    l1 += __shfl_xor_sync(0xffffffffu, l1, 1);
    l1 += __shfl_xor_sync(0xffffffffu, l1, 2);

    // ---- combine kpar halves through smem (loop's last barrier freed it) ----
    float* Cf = (float*)smraw;                   // [4][16][CPIT] floats
    float* Lf = (float*)(smraw + 4 * 16 * CPIT * 4);   // [64]

    if (kpar == 1) {
        float* C = Cf + rg * (16 * CPIT);
#pragma unroll
        for (int ni = 0; ni < 16; ni++) {
            int col = ni * 8 + 2 * t;
            *(float2*)&C[g * CPIT + col] =
                make_float2(accO[ni][0], accO[ni][1]);
            *(float2*)&C[(g + 8) * CPIT + col] =
                make_float2(accO[ni][2], accO[ni][3]);
        }
        if (t == 0) {
            Lf[rg * 16 + g]     = l0;
            Lf[rg * 16 + 8 + g] = l1;
        }
    }
    __syncthreads();

    if (kpar == 0) {
        float* C = Cf + rg * (16 * CPIT);
        const float inv0 = 1.0f / (l0 + Lf[rg * 16 + g]);
        const float inv1 = 1.0f / (l1 + Lf[rg * 16 + 8 + g]);

        const int b = bh >> 4, h = bh & 15;
        const int r0 = qt * 64 + rg * 16 + g;
        size_t ob0 = (((size_t)b * SS + r0) * HH + h) * EE;
        size_t ob1 = (((size_t)b * SS + r0 + 8) * HH + h) * EE;
#pragma unroll
        for (int ni = 0; ni < 16; ni++) {
            int col = ni * 8 + 2 * t;
            float2 c0 = *(float2*)&C[g * CPIT + col];
            float2 c1 = *(float2*)&C[(g + 8) * CPIT + col];
            *(float2*)&out[ob0 + col] =
                make_float2((accO[ni][0] + c0.x) * inv0,
                            (accO[ni][1] + c0.y) * inv0);
            *(float2*)&out[ob1 + col] =
                make_float2((accO[ni][2] + c1.x) * inv1,
                            (accO[ni][3] + c1.y) * inv1);
        }
    }
}

// ===========================================================================
extern "C" void kernel_launch(void* const* d_in, const int* in_sizes, int n_in,
                              void* d_out, int out_size)
{
    (void)in_sizes; (void)n_in; (void)out_size;
    const float* X    = (const float*)d_in[0];
    const float* W    = (const float*)d_in[1];
    const float* bias = (const float*)d_in[2];
    float* out = (float*)d_out;

    const int qkv_smem  = 2 * 128 * QPH * (int)sizeof(__half);   // 69632
    const int attn_smem = ATTN_SMEM;                             // 89088

    cudaFuncSetAttribute(qkv_kernel,
                         cudaFuncAttributeMaxDynamicSharedMemorySize, qkv_smem);
    cudaFuncSetAttribute(attn_kernel,
                         cudaFuncAttributeMaxDynamicSharedMemorySize, attn_smem);

    rope_table_kernel<<<(SS * 64 + 511) / 512, 512>>>();
    qkv_kernel<<<dim3(FF / 128, (BB * SS) / 128), 256, qkv_smem>>>(X, W, bias);
    attn_kernel<<<dim3(SS / 64, BHN), 256, attn_smem>>>(out);
}

// round 13
// speedup vs baseline: 1.0416x; 1.0416x over previous
#include <cuda_runtime.h>
#include <cuda_fp16.h>
#include <math.h>
#include <cstdint>

#define BB 8
#define SS 1024
#define EE 128
#define HH 16
#define BHN 128
#define FF 6144

#define QPH 136    // pitch (halves) for 128-wide half tiles
#define VPH 40     // pitch (halves) for 32-wide half tiles (V^T)
#define CPIT 132   // pitch (floats) for QKV C staging

// Scratch (fp16): q,k in [bh][s][d]; v transposed in [bh][d][s]
__device__ __half g_q [(size_t)BHN*SS*EE];
__device__ __half g_k [(size_t)BHN*SS*EE];
__device__ __half g_vT[(size_t)BHN*EE*SS];
__device__ float  g_cs[SS*64];
__device__ float  g_sn[SS*64];

__device__ __forceinline__ void mma16(float d[4], const uint32_t a[4],
                                      const uint32_t b[2]) {
    asm volatile(
        "mma.sync.aligned.m16n8k16.row.col.f32.f16.f16.f32 "
        "{%0,%1,%2,%3}, {%4,%5,%6,%7}, {%8,%9}, {%0,%1,%2,%3};"
        : "+f"(d[0]), "+f"(d[1]), "+f"(d[2]), "+f"(d[3])
        : "r"(a[0]), "r"(a[1]), "r"(a[2]), "r"(a[3]), "r"(b[0]), "r"(b[1]));
}

__device__ __forceinline__ uint32_t ldh2(const __half* p) {
    return *(const uint32_t*)p;
}

__device__ __forceinline__ uint32_t smem_u32(const void* p) {
    uint32_t a;
    asm("{ .reg .u64 t; cvta.to.shared.u64 t, %1; cvt.u32.u64 %0, t; }"
        : "=r"(a) : "l"(p));
    return a;
}

__device__ __forceinline__ void cpa16(uint32_t dst, const void* src) {
    asm volatile("cp.async.cg.shared.global [%0], [%1], 16;"
                 :: "r"(dst), "l"(src));
}
#define CP_COMMIT() asm volatile("cp.async.commit_group;" ::: "memory")
#define CP_WAIT0()  asm volatile("cp.async.wait_group 0;"  ::: "memory")

__device__ __forceinline__ uint4 pack8(float4 x, float4 y) {
    __half2 h0 = __floats2half2_rn(x.x, x.y);
    __half2 h1 = __floats2half2_rn(x.z, x.w);
    __half2 h2 = __floats2half2_rn(y.x, y.y);
    __half2 h3 = __floats2half2_rn(y.z, y.w);
    uint4 u;
    u.x = *(uint32_t*)&h0; u.y = *(uint32_t*)&h1;
    u.z = *(uint32_t*)&h2; u.w = *(uint32_t*)&h3;
    return u;
}

// ===========================================================================
// Kernel 0: RoPE table
// ===========================================================================
__global__ void rope_table_kernel() {
    int idx = blockIdx.x * blockDim.x + threadIdx.x;
    if (idx >= SS * 64) return;
    int s = idx >> 6, j = idx & 63;
    float invf = (float)pow(10000.0, -(double)j / 64.0);
    float ang = (float)s * invf;
    float sn, cs;
    sincosf(ang, &sn, &cs);
    g_cs[idx] = cs;
    g_sn[idx] = sn;
}

// ===========================================================================
// Kernel 1: QKV = X @ W^T + b (fp16 mma), fused RoPE, scatter q/k/vT.
// ===========================================================================
__global__ void __launch_bounds__(256, 2) qkv_kernel(
    const float* __restrict__ X, const float* __restrict__ W,
    const float* __restrict__ bias)
{
    extern __shared__ char smraw[];
    __half* Ah = (__half*)smraw;            // [128][QPH]
    __half* Bh = Ah + 128 * QPH;            // [128][QPH]
    float*  Cs = (float*)smraw;             // [128][CPIT] (reused after gemm)

    const int tid = threadIdx.x, wid = tid >> 5, lane = tid & 31;
    const int g = lane >> 2, t = lane & 3;
    const int wm = wid & 3, wn = wid >> 2;
    const int nt = blockIdx.x, mt = blockIdx.y;

    const float* Ag = X + (size_t)mt * 128 * EE;
    const float* Bg = W + (size_t)nt * 128 * EE;

#pragma unroll
    for (int i = 0; i < 8; i++) {
        int seg = tid + i * 256;
        int r = seg >> 4, c8 = (seg & 15) << 3;
        float4 a1 = *(const float4*)&Ag[r * EE + c8];
        float4 a2 = *(const float4*)&Ag[r * EE + c8 + 4];
        *(uint4*)&Ah[r * QPH + c8] = pack8(a1, a2);
        float4 b1 = *(const float4*)&Bg[r * EE + c8];
        float4 b2 = *(const float4*)&Bg[r * EE + c8 + 4];
        *(uint4*)&Bh[r * QPH + c8] = pack8(b1, b2);
    }
    __syncthreads();

    float acc[2][8][4];
#pragma unroll
    for (int mi = 0; mi < 2; mi++)
#pragma unroll
        for (int ni = 0; ni < 8; ni++)
#pragma unroll
            for (int ci = 0; ci < 4; ci++) acc[mi][ni][ci] = 0.0f;

    const __half* Ab = Ah + (wm * 32 + g) * QPH + 2 * t;
    const __half* Bb = Bh + (wn * 64 + g) * QPH + 2 * t;

#pragma unroll
    for (int k0 = 0; k0 < 8; k0++) {
        uint32_t af[2][4], bf[8][2];
#pragma unroll
        for (int mi = 0; mi < 2; mi++) {
            const __half* p = Ab + mi * 16 * QPH + k0 * 16;
            af[mi][0] = ldh2(p);
            af[mi][1] = ldh2(p + 8 * QPH);
            af[mi][2] = ldh2(p + 8);
            af[mi][3] = ldh2(p + 8 * QPH + 8);
        }
#pragma unroll
        for (int ni = 0; ni < 8; ni++) {
            const __half* p = Bb + ni * 8 * QPH + k0 * 16;
            bf[ni][0] = ldh2(p);
            bf[ni][1] = ldh2(p + 8);
        }
#pragma unroll
        for (int mi = 0; mi < 2; mi++)
#pragma unroll
            for (int ni = 0; ni < 8; ni++)
                mma16(acc[mi][ni], af[mi], bf[ni]);
    }
    __syncthreads();

#pragma unroll
    for (int mi = 0; mi < 2; mi++)
#pragma unroll
        for (int ni = 0; ni < 8; ni++) {
            int row = wm * 32 + mi * 16 + g;
            int col = wn * 64 + ni * 8 + t * 2;
            *(float2*)&Cs[row * CPIT + col] =
                make_float2(acc[mi][ni][0], acc[mi][ni][1]);
            *(float2*)&Cs[(row + 8) * CPIT + col] =
                make_float2(acc[mi][ni][2], acc[mi][ni][3]);
        }
    __syncthreads();

    const int c = nt >> 4, h = nt & 15;
    const float* bptr = bias + nt * 128;
    const int bidx = (mt * 128) >> 10;
    const int s_base = (mt * 128) & 1023;

    if (c == 2) {
        size_t vb = ((size_t)(bidx * HH + h)) * EE * SS;
#pragma unroll
        for (int it = 0; it < 16; it++) {
            int d = it * 8 + wid;
            float bd = bptr[d];
#pragma unroll
            for (int q = 0; q < 4; q++) {
                int r = q * 32 + lane;
                g_vT[vb + (size_t)d * SS + s_base + r] =
                    __float2half_rn(Cs[r * CPIT + d] + bd);
            }
        }
    } else {
        __half* dst = (c == 0) ? g_q : g_k;
        const int row = tid >> 1, part = tid & 1;
        const int s = s_base + row;
        size_t rb = (((size_t)(bidx * HH + h)) * SS + s) * EE;
#pragma unroll
        for (int jq = 0; jq < 8; jq++) {
            int j = part * 32 + jq * 4;
            float4 x1 = *(float4*)&Cs[row * CPIT + j];
            float4 x2 = *(float4*)&Cs[row * CPIT + 64 + j];
            float4 b1 = *(const float4*)&bptr[j];
            float4 b2 = *(const float4*)&bptr[64 + j];
            float4 cs4 = *(const float4*)&g_cs[s * 64 + j];
            float4 sn4 = *(const float4*)&g_sn[s * 64 + j];
            x1.x += b1.x; x1.y += b1.y; x1.z += b1.z; x1.w += b1.w;
            x2.x += b2.x; x2.y += b2.y; x2.z += b2.z; x2.w += b2.w;
            __half2 o1a = __floats2half2_rn(x1.x * cs4.x - x2.x * sn4.x,
                                            x1.y * cs4.y - x2.y * sn4.y);
            __half2 o1b = __floats2half2_rn(x1.z * cs4.z - x2.z * sn4.z,
                                            x1.w * cs4.w - x2.w * sn4.w);
            __half2 o2a = __floats2half2_rn(x1.x * sn4.x + x2.x * cs4.x,
                                            x1.y * sn4.y + x2.y * cs4.y);
            __half2 o2b = __floats2half2_rn(x1.z * sn4.z + x2.z * cs4.z,
                                            x1.w * sn4.w + x2.w * cs4.w);
            uint2 u1 = make_uint2(*(uint32_t*)&o1a, *(uint32_t*)&o1b);
            uint2 u2 = make_uint2(*(uint32_t*)&o2a, *(uint32_t*)&o2b);
            *(uint2*)&dst[rb + j]      = u1;
            *(uint2*)&dst[rb + 64 + j] = u2;
        }
    }
}

// ===========================================================================
// Kernel 2: attention (fp16 mma, FA2 register-P, softmax software-pipelined).
// CTA = 128 q rows of one (b,h); 32 key tiles of 32. K double-buffered,
// V TRIPLE-buffered (gemm2 of kt-1 runs in iteration kt). Iteration kt:
//   prefetch(kt+1) -> gemm1(kt) -> gemm2(kt-1, P from regs) -> exp(kt) ->
//   wait + barrier.
// Tensor pipe never stalls on MUFU: exp(kt) overlaps next iter's gemms of
// other warps / the wait shadow.
// ===========================================================================
#define AQ_OFF   0
#define AK_OFF   34816                       // 2 x [32][QPH] halves (8704 ea)
#define AV_OFF   (34816 + 17408)             // 3 x [128][VPH] halves (10240 ea)
#define ATTN_SMEM (AV_OFF + 3*10240)         // 82944

__global__ void __launch_bounds__(256, 2) attn_kernel(float* __restrict__ out)
{
    extern __shared__ char smraw[];
    __half* Qs = (__half*)(smraw + AQ_OFF);
    __half* Ks = (__half*)(smraw + AK_OFF);
    __half* Vs = (__half*)(smraw + AV_OFF);
    const uint32_t sb = smem_u32(smraw);

    const int tid = threadIdx.x, wid = tid >> 5, lane = tid & 31;
    const int g = lane >> 2, t = lane & 3;
    const int qt = blockIdx.x, bh = blockIdx.y;

    const __half* qg = g_q  + (size_t)bh * SS * EE + (size_t)qt * 128 * EE;
    const __half* kg = g_k  + (size_t)bh * SS * EE;
    const __half* vg = g_vT + (size_t)bh * EE * SS;

    // cp.async segments: K tile 32x128h = 512 16B chunks; V tile 128x32h = 512
    const int ks0 = tid,       ks1 = tid + 256;
    const int kr0 = ks0 >> 4,  kc0 = (ks0 & 15) << 3;
    const int kr1 = ks1 >> 4,  kc1 = (ks1 & 15) << 3;
    const int vr0 = ks0 >> 2,  vc0 = (ks0 & 3) << 3;
    const int vr1 = ks1 >> 2,  vc1 = (ks1 & 3) << 3;

    const uint32_t kd0 = sb + AK_OFF + (kr0 * QPH + kc0) * 2;
    const uint32_t kd1 = sb + AK_OFF + (kr1 * QPH + kc1) * 2;
    const uint32_t vd0 = sb + AV_OFF + (vr0 * VPH + vc0) * 2;
    const uint32_t vd1 = sb + AV_OFF + (vr1 * VPH + vc1) * 2;

    // ---- prologue: K/V tile 0 (cp.async) + Q tile (regular) ----
    cpa16(kd0, kg + (size_t)kr0 * EE + kc0);
    cpa16(kd1, kg + (size_t)kr1 * EE + kc1);
    cpa16(vd0, vg + (size_t)vr0 * SS + vc0);
    cpa16(vd1, vg + (size_t)vr1 * SS + vc1);
    CP_COMMIT();

#pragma unroll
    for (int i = 0; i < 8; i++) {
        int seg = tid + i * 256;
        int r = seg >> 4, c8 = (seg & 15) << 3;
        *(uint4*)&Qs[r * QPH + c8] = *(const uint4*)&qg[r * EE + c8];
    }
    CP_WAIT0();
    __syncthreads();

    float accO[16][4];
#pragma unroll
    for (int ni = 0; ni < 16; ni++)
#pragma unroll
        for (int ci = 0; ci < 4; ci++) accO[ni][ci] = 0.0f;
    float l0 = 0.0f, l1 = 0.0f;

    const float scl = 0.08838834764831845f;  // 1/sqrt(128)

    const __half* QA = Qs + (16 * wid + g) * QPH + 2 * t;

    uint32_t pa_prev[2][4];   // carried P fragment (exp'd scores of kt-1)

    for (int kt = 0; kt < 32; kt++) {
        // ---- prefetch tile kt+1 (K double-buffer, V triple-buffer) ----
        if (kt < 31) {
            const __half* kgn = kg + (size_t)(kt + 1) * 32 * EE;
            const __half* vgn = vg + (kt + 1) * 32;
            const uint32_t kb = ((kt + 1) & 1) * 8704u;
            const uint32_t vb = (uint32_t)(((kt + 1) % 3) * 10240);
            cpa16(kd0 + kb, kgn + (size_t)kr0 * EE + kc0);
            cpa16(kd1 + kb, kgn + (size_t)kr1 * EE + kc1);
            cpa16(vd0 + vb, vgn + (size_t)vr0 * SS + vc0);
            cpa16(vd1 + vb, vgn + (size_t)vr1 * SS + vc1);
            CP_COMMIT();
        }

        const __half* KB = Ks + (kt & 1) * (32 * QPH) + g * QPH + 2 * t;

        // ---- gemm1: S(16 rows x 32 keys/warp) = Q . K^T over d=128 ----
        float sc[4][4];
#pragma unroll
        for (int ni = 0; ni < 4; ni++)
#pragma unroll
            for (int ci = 0; ci < 4; ci++) sc[ni][ci] = 0.0f;

#pragma unroll
        for (int k0 = 0; k0 < 8; k0++) {
            uint32_t af[4];
            {
                const __half* p = QA + k0 * 16;
                af[0] = ldh2(p);
                af[1] = ldh2(p + 8 * QPH);
                af[2] = ldh2(p + 8);
                af[3] = ldh2(p + 8 * QPH + 8);
            }
#pragma unroll
            for (int ni = 0; ni < 4; ni++) {
                const __half* p = KB + ni * 8 * QPH + k0 * 16;
                uint32_t bf[2] = {ldh2(p), ldh2(p + 8)};
                mma16(sc[ni], af, bf);
            }
        }

        // ---- gemm2 for tile kt-1 (P carried in registers) ----
        if (kt > 0) {
            const __half* VB = Vs + ((kt + 2) % 3) * (128 * VPH)   // (kt-1)%3
                                  + g * VPH + 2 * t;
#pragma unroll
            for (int kg2 = 0; kg2 < 2; kg2++) {
#pragma unroll
                for (int ni = 0; ni < 16; ni++) {
                    const __half* p = VB + ni * 8 * VPH + kg2 * 16;
                    uint32_t bf[2] = {ldh2(p), ldh2(p + 8)};
                    mma16(accO[ni], pa_prev[kg2], bf);
                }
            }
        }

        // ---- exp(kt) -> pa_prev (consumed next iteration) ----
#pragma unroll
        for (int ni = 0; ni < 4; ni++) {
            float p0 = __expf(sc[ni][0] * scl);
            float p1 = __expf(sc[ni][1] * scl);
            float p2 = __expf(sc[ni][2] * scl);
            float p3 = __expf(sc[ni][3] * scl);
            l0 += p0 + p1;
            l1 += p2 + p3;
            __half2 hA = __floats2half2_rn(p0, p1);
            __half2 hB = __floats2half2_rn(p2, p3);
            const int kg2 = ni >> 1, pos = ni & 1;
            pa_prev[kg2][2 * pos + 0] = *(uint32_t*)&hA;
            pa_prev[kg2][2 * pos + 1] = *(uint32_t*)&hB;
        }

        CP_WAIT0();
        __syncthreads();
    }

    // ---- flush gemm2 for the last tile (kt=31) ----
    {
        const __half* VB = Vs + (31 % 3) * (128 * VPH) + g * VPH + 2 * t;
#pragma unroll
        for (int kg2 = 0; kg2 < 2; kg2++) {
#pragma unroll
            for (int ni = 0; ni < 16; ni++) {
                const __half* p = VB + ni * 8 * VPH + kg2 * 16;
                uint32_t bf[2] = {ldh2(p), ldh2(p + 8)};
                mma16(accO[ni], pa_prev[kg2], bf);
            }
        }
    }

    // ---- row sums: quad reduction (rows warp-private) ----
    l0 += __shfl_xor_sync(0xffffffffu, l0, 1);
    l0 += __shfl_xor_sync(0xffffffffu, l0, 2);
    l1 += __shfl_xor_sync(0xffffffffu, l1, 1);
    l1 += __shfl_xor_sync(0xffffffffu, l1, 2);
    const float inv0 = 1.0f / l0, inv1 = 1.0f / l1;

    // ---- epilogue: out[b][s][h][d] ----
    const int b = bh >> 4, h = bh & 15;
    const int r0 = 16 * wid + g;
    size_t ob0 = (((size_t)b * SS + qt * 128 + r0) * HH + h) * EE;
    size_t ob1 = (((size_t)b * SS + qt * 128 + r0 + 8) * HH + h) * EE;
#pragma unroll
    for (int ni = 0; ni < 16; ni++) {
        int col = ni * 8 + 2 * t;
        *(float2*)&out[ob0 + col] =
            make_float2(accO[ni][0] * inv0, accO[ni][1] * inv0);
        *(float2*)&out[ob1 + col] =
            make_float2(accO[ni][2] * inv1, accO[ni][3] * inv1);
    }
}

// ===========================================================================
extern "C" void kernel_launch(void* const* d_in, const int* in_sizes, int n_in,
                              void* d_out, int out_size)
{
    (void)in_sizes; (void)n_in; (void)out_size;
    const float* X    = (const float*)d_in[0];
    const float* W    = (const float*)d_in[1];
    const float* bias = (const float*)d_in[2];
    float* out = (float*)d_out;

    const int qkv_smem  = 2 * 128 * QPH * (int)sizeof(__half);   // 69632
    const int attn_smem = ATTN_SMEM;                             // 82944

    cudaFuncSetAttribute(qkv_kernel,
                         cudaFuncAttributeMaxDynamicSharedMemorySize, qkv_smem);
    cudaFuncSetAttribute(attn_kernel,
                         cudaFuncAttributeMaxDynamicSharedMemorySize, attn_smem);

    rope_table_kernel<<<(SS * 64 + 511) / 512, 512>>>();
    qkv_kernel<<<dim3(FF / 128, (BB * SS) / 128), 256, qkv_smem>>>(X, W, bias);
    attn_kernel<<<dim3(SS / 128, BHN), 256, attn_smem>>>(out);
}